// round 1
// baseline (speedup 1.0000x reference)
#include <cuda_runtime.h>
#include <cstdint>
#include <math.h>

// ---------------------------------------------------------------------------
// PyramidResidualMoE: out = x + baseSwiGLU(x) + expert_{argmax}(x)
// (router weight provably == 1.0 for the top-1 expert; see analysis)
// ---------------------------------------------------------------------------

#define N_TOK 16384
#define C_DIM 896
#define HB    1152
#define HMAX  1536
#define NEXP  3

#define BM 128
#define BN 64
#define BK 32
#define LDS 36   // padded smem row stride (floats): conflict-free fragment loads, 16B-aligned

// scratch (device-global: no allocations allowed)
__device__ float g_baseH[(size_t)N_TOK * HB];    // base hidden activations
__device__ float g_expH[(size_t)N_TOK * HMAX];   // expert hidden activations (indexed by token)
__device__ int   g_idx[NEXP][N_TOK];             // gathered token lists
__device__ int   g_count[NEXP];

// ---------------------------------------------------------------------------
__global__ void zero_counts_kernel() {
    if (threadIdx.x < NEXP) g_count[threadIdx.x] = 0;
}

__global__ void router_kernel(const float* __restrict__ x,
                              const float* __restrict__ rw,
                              const float* __restrict__ bias) {
    int tok  = blockIdx.x * blockDim.y + threadIdx.y;
    int lane = threadIdx.x;
    if (tok >= N_TOK) return;
    const float* xr = x + (size_t)tok * C_DIM;
    float s0 = 0.f, s1 = 0.f, s2 = 0.f;
    for (int c = lane; c < C_DIM; c += 32) {
        float xv = xr[c];
        s0 = fmaf(xv, rw[c], s0);
        s1 = fmaf(xv, rw[C_DIM + c], s1);
        s2 = fmaf(xv, rw[2 * C_DIM + c], s2);
    }
#pragma unroll
    for (int o = 16; o > 0; o >>= 1) {
        s0 += __shfl_xor_sync(0xffffffffu, s0, o);
        s1 += __shfl_xor_sync(0xffffffffu, s1, o);
        s2 += __shfl_xor_sync(0xffffffffu, s2, o);
    }
    if (lane == 0) {
        float l0 = s0 + bias[0], l1 = s1 + bias[1], l2 = s2 + bias[2];
        int best = 0; float bv = l0;
        if (l1 > bv) { best = 1; bv = l1; }   // strict > : first-occurrence argmax
        if (l2 > bv) { best = 2; bv = l2; }
        int pos = atomicAdd(&g_count[best], 1);
        g_idx[best][pos] = tok;
    }
}

// ---------------------------------------------------------------------------
__device__ __forceinline__ uint32_t f2tf(float f) {
    uint32_t u;
    asm("cvt.rna.tf32.f32 %0, %1;" : "=r"(u) : "f"(f));
    return u;
}

__device__ __forceinline__ void mma8(float* c,
                                     uint32_t a0, uint32_t a1, uint32_t a2, uint32_t a3,
                                     uint32_t b0, uint32_t b1) {
    asm volatile(
        "mma.sync.aligned.m16n8k8.row.col.f32.tf32.tf32.f32 "
        "{%0,%1,%2,%3}, {%4,%5,%6,%7}, {%8,%9}, {%0,%1,%2,%3};"
        : "+f"(c[0]), "+f"(c[1]), "+f"(c[2]), "+f"(c[3])
        : "r"(a0), "r"(a1), "r"(a2), "r"(a3), "r"(b0), "r"(b1));
}

__device__ __forceinline__ void cp16(uint32_t dst, const void* src) {
    asm volatile("cp.async.cg.shared.global [%0], [%1], 16;" :: "r"(dst), "l"(src) : "memory");
}
__device__ __forceinline__ void cp_commit() {
    asm volatile("cp.async.commit_group;" ::: "memory");
}

__device__ __forceinline__ float silu_f(float g) {
    return g / (1.f + expf(-g)) ;
}

// ---------------------------------------------------------------------------
// Fused layer-1: H[t, n] = silu(X·Gw^T) * (X·Uw^T).  A = x rows (gathered for
// experts), B = weights [H, C] row-major (K-major).  Writes fp32 scratch.
// ---------------------------------------------------------------------------
template <bool GATHER>
__global__ void __launch_bounds__(256)
mlp_up_kernel(const float* __restrict__ x,
              const float* __restrict__ gw,
              const float* __restrict__ uw,
              int expert) {
    extern __shared__ float sm[];
    const int tid  = threadIdx.x;
    const int lane = tid & 31;
    const int wid  = tid >> 5;
    const int wm   = (wid & 1) * 64;
    const int wn   = (wid >> 1) * 16;
    const int m0   = blockIdx.y * BM;
    const int n0   = blockIdx.x * BN;

    const int M = GATHER ? g_count[expert] : N_TOK;
    if (m0 >= M) return;
    const int* idx = GATHER ? g_idx[expert] : nullptr;
    float* hout          = GATHER ? g_expH : g_baseH;
    const int out_stride = GATHER ? HMAX : HB;

    const int STG = (BM + 2 * BN) * LDS;  // floats per stage
    uint32_t sbase = (uint32_t)__cvta_generic_to_shared(sm);

    // per-thread load descriptors (computed once)
    const float* a_src[4]; uint32_t a_off[4];
#pragma unroll
    for (int t = 0; t < 4; ++t) {
        int f = tid + 256 * t;
        int r = f >> 3, c4 = f & 7;
        int gr = m0 + r;
        int tok = GATHER ? idx[min(gr, M - 1)] : min(gr, M - 1);
        a_src[t] = x + (size_t)tok * C_DIM + c4 * 4;
        a_off[t] = (uint32_t)(r * LDS + c4 * 4) * 4u;
    }
    const float* bg_src[2]; const float* bu_src[2]; uint32_t b_off[2];
#pragma unroll
    for (int t = 0; t < 2; ++t) {
        int f = tid + 256 * t;
        int r = f >> 3, c4 = f & 7;
        bg_src[t] = gw + (size_t)(n0 + r) * C_DIM + c4 * 4;
        bu_src[t] = uw + (size_t)(n0 + r) * C_DIM + c4 * 4;
        b_off[t] = (uint32_t)(r * LDS + c4 * 4) * 4u;
    }

    auto prefetch = [&](int kt, int s) {
        uint32_t sa = sbase + (uint32_t)(s * STG) * 4u;
        uint32_t sg = sa + (uint32_t)(BM * LDS) * 4u;
        uint32_t su = sg + (uint32_t)(BN * LDS) * 4u;
#pragma unroll
        for (int t = 0; t < 4; ++t) cp16(sa + a_off[t], a_src[t] + kt * BK);
#pragma unroll
        for (int t = 0; t < 2; ++t) {
            cp16(sg + b_off[t], bg_src[t] + kt * BK);
            cp16(su + b_off[t], bu_src[t] + kt * BK);
        }
        cp_commit();
    };

    float accg[4][2][4] = {};
    float accu[4][2][4] = {};

    const int KT = C_DIM / BK;  // 28
    prefetch(0, 0);
    for (int kt = 0; kt < KT; ++kt) {
        int cur = kt & 1;
        if (kt + 1 < KT) {
            prefetch(kt + 1, cur ^ 1);
            asm volatile("cp.async.wait_group 1;" ::: "memory");
        } else {
            asm volatile("cp.async.wait_group 0;" ::: "memory");
        }
        __syncthreads();
        const float* as = sm + cur * STG;
        const float* bg = as + BM * LDS;
        const float* bu = bg + BN * LDS;
#pragma unroll
        for (int ks = 0; ks < 4; ++ks) {
            int kk = ks * 8 + (lane & 3);
            uint32_t a[4][4];
#pragma unroll
            for (int mi = 0; mi < 4; ++mi) {
                int m = wm + mi * 16 + (lane >> 2);
                a[mi][0] = f2tf(as[m * LDS + kk]);
                a[mi][1] = f2tf(as[(m + 8) * LDS + kk]);
                a[mi][2] = f2tf(as[m * LDS + kk + 4]);
                a[mi][3] = f2tf(as[(m + 8) * LDS + kk + 4]);
            }
            uint32_t fg[2][2], fu[2][2];
#pragma unroll
            for (int ni = 0; ni < 2; ++ni) {
                int n = wn + ni * 8 + (lane >> 2);
                fg[ni][0] = f2tf(bg[n * LDS + kk]);
                fg[ni][1] = f2tf(bg[n * LDS + kk + 4]);
                fu[ni][0] = f2tf(bu[n * LDS + kk]);
                fu[ni][1] = f2tf(bu[n * LDS + kk + 4]);
            }
#pragma unroll
            for (int mi = 0; mi < 4; ++mi)
#pragma unroll
                for (int ni = 0; ni < 2; ++ni) {
                    mma8(accg[mi][ni], a[mi][0], a[mi][1], a[mi][2], a[mi][3], fg[ni][0], fg[ni][1]);
                    mma8(accu[mi][ni], a[mi][0], a[mi][1], a[mi][2], a[mi][3], fu[ni][0], fu[ni][1]);
                }
        }
        __syncthreads();
    }

    // epilogue: silu(g)*u -> scratch
#pragma unroll
    for (int mi = 0; mi < 4; ++mi)
#pragma unroll
        for (int half = 0; half < 2; ++half) {
            int m  = wm + mi * 16 + (lane >> 2) + half * 8;
            int gr = m0 + m;
            if (gr < M) {
                int tok = GATHER ? idx[gr] : gr;
                float* orow = hout + (size_t)tok * out_stride;
#pragma unroll
                for (int ni = 0; ni < 2; ++ni) {
                    int n = n0 + wn + ni * 8 + 2 * (lane & 3);
                    float g0 = accg[mi][ni][half * 2 + 0];
                    float g1 = accg[mi][ni][half * 2 + 1];
                    float u0 = accu[mi][ni][half * 2 + 0];
                    float u1 = accu[mi][ni][half * 2 + 1];
                    float2 v = make_float2(silu_f(g0) * u0, silu_f(g1) * u1);
                    *reinterpret_cast<float2*>(orow + n) = v;
                }
            }
        }
}

// ---------------------------------------------------------------------------
// Down projection.  Base: out[t,:] = x[t,:] + H·Dw^T.  Expert: out[tok,:] += ...
// Dw row-major [C, K]  (K = hidden width).
// ---------------------------------------------------------------------------
template <bool GATHER>
__global__ void __launch_bounds__(256)
down_kernel(const float* __restrict__ dw,
            const float* __restrict__ x,
            float* __restrict__ out,
            int K, int expert) {
    extern __shared__ float sm[];
    const int tid  = threadIdx.x;
    const int lane = tid & 31;
    const int wid  = tid >> 5;
    const int wm   = (wid & 1) * 64;
    const int wn   = (wid >> 1) * 16;
    const int m0   = blockIdx.y * BM;
    const int n0   = blockIdx.x * BN;

    const int M = GATHER ? g_count[expert] : N_TOK;
    if (m0 >= M) return;
    const int* idx = GATHER ? g_idx[expert] : nullptr;
    const float* hbuf = GATHER ? g_expH : g_baseH;
    const int lda = GATHER ? HMAX : HB;

    const int STG = (BM + BN) * LDS;
    uint32_t sbase = (uint32_t)__cvta_generic_to_shared(sm);

    const float* a_src[4]; uint32_t a_off[4];
#pragma unroll
    for (int t = 0; t < 4; ++t) {
        int f = tid + 256 * t;
        int r = f >> 3, c4 = f & 7;
        int gr = m0 + r;
        int tok = GATHER ? idx[min(gr, M - 1)] : min(gr, M - 1);
        a_src[t] = hbuf + (size_t)tok * lda + c4 * 4;
        a_off[t] = (uint32_t)(r * LDS + c4 * 4) * 4u;
    }
    const float* b_src[2]; uint32_t b_off[2];
#pragma unroll
    for (int t = 0; t < 2; ++t) {
        int f = tid + 256 * t;
        int r = f >> 3, c4 = f & 7;
        b_src[t] = dw + (size_t)(n0 + r) * K + c4 * 4;
        b_off[t] = (uint32_t)((BM + r) * LDS + c4 * 4) * 4u;
    }

    auto prefetch = [&](int kt, int s) {
        uint32_t sa = sbase + (uint32_t)(s * STG) * 4u;
#pragma unroll
        for (int t = 0; t < 4; ++t) cp16(sa + a_off[t], a_src[t] + kt * BK);
#pragma unroll
        for (int t = 0; t < 2; ++t) cp16(sa + b_off[t], b_src[t] + kt * BK);
        cp_commit();
    };

    float acc[4][2][4] = {};
    const int KT = K / BK;
    prefetch(0, 0);
    for (int kt = 0; kt < KT; ++kt) {
        int cur = kt & 1;
        if (kt + 1 < KT) {
            prefetch(kt + 1, cur ^ 1);
            asm volatile("cp.async.wait_group 1;" ::: "memory");
        } else {
            asm volatile("cp.async.wait_group 0;" ::: "memory");
        }
        __syncthreads();
        const float* as = sm + cur * STG;
        const float* bs = as + BM * LDS;
#pragma unroll
        for (int ks = 0; ks < 4; ++ks) {
            int kk = ks * 8 + (lane & 3);
            uint32_t a[4][4];
#pragma unroll
            for (int mi = 0; mi < 4; ++mi) {
                int m = wm + mi * 16 + (lane >> 2);
                a[mi][0] = f2tf(as[m * LDS + kk]);
                a[mi][1] = f2tf(as[(m + 8) * LDS + kk]);
                a[mi][2] = f2tf(as[m * LDS + kk + 4]);
                a[mi][3] = f2tf(as[(m + 8) * LDS + kk + 4]);
            }
            uint32_t b[2][2];
#pragma unroll
            for (int ni = 0; ni < 2; ++ni) {
                int n = wn + ni * 8 + (lane >> 2);
                b[ni][0] = f2tf(bs[n * LDS + kk]);
                b[ni][1] = f2tf(bs[n * LDS + kk + 4]);
            }
#pragma unroll
            for (int mi = 0; mi < 4; ++mi)
#pragma unroll
                for (int ni = 0; ni < 2; ++ni)
                    mma8(acc[mi][ni], a[mi][0], a[mi][1], a[mi][2], a[mi][3], b[ni][0], b[ni][1]);
        }
        __syncthreads();
    }

#pragma unroll
    for (int mi = 0; mi < 4; ++mi)
#pragma unroll
        for (int half = 0; half < 2; ++half) {
            int m  = wm + mi * 16 + (lane >> 2) + half * 8;
            int gr = m0 + m;
            if (gr < M) {
                int tok = GATHER ? idx[gr] : gr;
                float* orow = out + (size_t)tok * C_DIM;
                const float* xrow = x + (size_t)tok * C_DIM;
#pragma unroll
                for (int ni = 0; ni < 2; ++ni) {
                    int n = n0 + wn + ni * 8 + 2 * (lane & 3);
                    float2 v = make_float2(acc[mi][ni][half * 2 + 0],
                                           acc[mi][ni][half * 2 + 1]);
                    if (GATHER) {
                        float2 old = *reinterpret_cast<const float2*>(orow + n);
                        v.x += old.x; v.y += old.y;
                    } else {
                        float2 xv = *reinterpret_cast<const float2*>(xrow + n);
                        v.x += xv.x; v.y += xv.y;
                    }
                    *reinterpret_cast<float2*>(orow + n) = v;
                }
            }
        }
}

// ---------------------------------------------------------------------------
extern "C" void kernel_launch(void* const* d_in, const int* in_sizes, int n_in,
                              void* d_out, int out_size) {
    const float* x    = (const float*)d_in[0];
    const float* bgw  = (const float*)d_in[1];
    const float* buw  = (const float*)d_in[2];
    const float* bdw  = (const float*)d_in[3];
    const float* rw   = (const float*)d_in[4];
    const float* bias = (const float*)d_in[5];
    const float* egw[NEXP] = {(const float*)d_in[6],  (const float*)d_in[9],  (const float*)d_in[12]};
    const float* euw[NEXP] = {(const float*)d_in[7],  (const float*)d_in[10], (const float*)d_in[13]};
    const float* edw[NEXP] = {(const float*)d_in[8],  (const float*)d_in[11], (const float*)d_in[14]};
    float* out = (float*)d_out;
    const int He[NEXP] = {1152, 1344, 1536};

    const int SMEM_L1 = 2 * (BM + 2 * BN) * LDS * 4;  // 73728 B
    const int SMEM_DN = 2 * (BM + BN) * LDS * 4;      // 55296 B
    cudaFuncSetAttribute(mlp_up_kernel<false>, cudaFuncAttributeMaxDynamicSharedMemorySize, SMEM_L1);
    cudaFuncSetAttribute(mlp_up_kernel<true>,  cudaFuncAttributeMaxDynamicSharedMemorySize, SMEM_L1);
    cudaFuncSetAttribute(down_kernel<false>,   cudaFuncAttributeMaxDynamicSharedMemorySize, SMEM_DN);
    cudaFuncSetAttribute(down_kernel<true>,    cudaFuncAttributeMaxDynamicSharedMemorySize, SMEM_DN);

    // 1) router
    zero_counts_kernel<<<1, 32>>>();
    router_kernel<<<N_TOK / 8, dim3(32, 8)>>>(x, rw, bias);

    // 2) layer-1 (gate/up fused)
    mlp_up_kernel<false><<<dim3(HB / BN, N_TOK / BM), 256, SMEM_L1>>>(x, bgw, buw, 0);
    for (int e = 0; e < NEXP; ++e)
        mlp_up_kernel<true><<<dim3(He[e] / BN, N_TOK / BM), 256, SMEM_L1>>>(x, egw[e], euw[e], e);

    // 3) down projection: base writes out = x + base, experts accumulate
    down_kernel<false><<<dim3(C_DIM / BN, N_TOK / BM), 256, SMEM_DN>>>(bdw, x, out, HB, 0);
    for (int e = 0; e < NEXP; ++e)
        down_kernel<true><<<dim3(C_DIM / BN, N_TOK / BM), 256, SMEM_DN>>>(edw[e], x, out, He[e], e);
}

// round 5
// speedup vs baseline: 1.5026x; 1.5026x over previous
#include <cuda_runtime.h>
#include <cuda_fp16.h>
#include <cstdint>
#include <math.h>

// ---------------------------------------------------------------------------
// PyramidResidualMoE, sm_100 legacy path (no tcgen05 available under
// compute_100 virtual arch): fp16 mma.m16n8k16 + ldmatrix + cp.async.
// out = x + baseSwiGLU(x) + expert_{argmax}(x)   (router weight provably 1.0)
// ---------------------------------------------------------------------------

#define N_TOK 16384
#define C_DIM 896
#define HMAX  1536
#define NEXP  3

// fp16 scratch (static device arrays; no allocations allowed)
__device__ __half g_xh[(size_t)N_TOK * C_DIM];          // x in fp16
__device__ __half g_hh[(size_t)N_TOK * HMAX];           // hidden activations
__device__ __half g_wh[13934592];                       // all weights fp16
__device__ int    g_idx[NEXP][N_TOK];
__device__ int    g_count[NEXP];

// offsets into g_wh (halves)
#define OFF_BG  0
#define OFF_BU  1032192
#define OFF_BD  2064384
#define OFF_E0G 3096576
#define OFF_E0U 4128768
#define OFF_E0D 5160960
#define OFF_E1G 6193152
#define OFF_E1U 7397376
#define OFF_E1D 8601600
#define OFF_E2G 9805824
#define OFF_E2U 11182080
#define OFF_E2D 12558336

// ---------------------------- PTX helpers ----------------------------------
__device__ __forceinline__ uint32_t smem_u32(const void* p) {
    uint32_t a;
    asm("{ .reg .u64 t; cvta.to.shared.u64 t, %1; cvt.u32.u64 %0, t; }" : "=r"(a) : "l"(p));
    return a;
}
__device__ __forceinline__ void cp16(uint32_t d, const void* s) {
    asm volatile("cp.async.cg.shared.global [%0], [%1], 16;" :: "r"(d), "l"(s) : "memory");
}
__device__ __forceinline__ void cp_commit() { asm volatile("cp.async.commit_group;" ::: "memory"); }
template<int N> __device__ __forceinline__ void cp_wait() {
    asm volatile("cp.async.wait_group %0;" :: "n"(N) : "memory");
}
__device__ __forceinline__ void ldsm4(uint32_t* r, uint32_t addr) {
    asm volatile("ldmatrix.sync.aligned.m8n8.x4.shared.b16 {%0,%1,%2,%3}, [%4];"
                 : "=r"(r[0]), "=r"(r[1]), "=r"(r[2]), "=r"(r[3]) : "r"(addr));
}
__device__ __forceinline__ void mma16816(float* c, const uint32_t* a, uint32_t b0, uint32_t b1) {
    asm volatile(
        "mma.sync.aligned.m16n8k16.row.col.f32.f16.f16.f32 "
        "{%0,%1,%2,%3}, {%4,%5,%6,%7}, {%8,%9}, {%0,%1,%2,%3};"
        : "+f"(c[0]), "+f"(c[1]), "+f"(c[2]), "+f"(c[3])
        : "r"(a[0]), "r"(a[1]), "r"(a[2]), "r"(a[3]), "r"(b0), "r"(b1));
}
__device__ __forceinline__ float silu_f(float g) { return g / (1.f + expf(-g)); }

// ---------------------------------------------------------------------------
__global__ void zero_counts_kernel() {
    if (threadIdx.x < NEXP) g_count[threadIdx.x] = 0;
}

__global__ void router_kernel(const float* __restrict__ x,
                              const float* __restrict__ rw,
                              const float* __restrict__ bias) {
    int tok  = blockIdx.x * blockDim.y + threadIdx.y;
    int lane = threadIdx.x;
    if (tok >= N_TOK) return;
    const float* xr = x + (size_t)tok * C_DIM;
    float s0 = 0.f, s1 = 0.f, s2 = 0.f;
    for (int c = lane; c < C_DIM; c += 32) {
        float xv = xr[c];
        s0 = fmaf(xv, rw[c], s0);
        s1 = fmaf(xv, rw[C_DIM + c], s1);
        s2 = fmaf(xv, rw[2 * C_DIM + c], s2);
    }
#pragma unroll
    for (int o = 16; o > 0; o >>= 1) {
        s0 += __shfl_xor_sync(0xffffffffu, s0, o);
        s1 += __shfl_xor_sync(0xffffffffu, s1, o);
        s2 += __shfl_xor_sync(0xffffffffu, s2, o);
    }
    if (lane == 0) {
        float l0 = s0 + bias[0], l1 = s1 + bias[1], l2 = s2 + bias[2];
        int best = 0; float bv = l0;
        if (l1 > bv) { best = 1; bv = l1; }
        if (l2 > bv) { best = 2; bv = l2; }
        int pos = atomicAdd(&g_count[best], 1);
        g_idx[best][pos] = tok;
    }
}

// ---------------------------------------------------------------------------
__global__ void cvt_x_kernel(const float* __restrict__ src, int n4) {
    int i = blockIdx.x * 256 + threadIdx.x;
    if (i >= n4) return;
    float4 v = reinterpret_cast<const float4*>(src)[i];
    __half2* d = reinterpret_cast<__half2*>(g_xh) + 2 * i;
    d[0] = __floats2half2_rn(v.x, v.y);
    d[1] = __floats2half2_rn(v.z, v.w);
}
__global__ void cvt_w_kernel(const float* __restrict__ src, int off, int n4) {
    int i = blockIdx.x * 256 + threadIdx.x;
    if (i >= n4) return;
    float4 v = reinterpret_cast<const float4*>(src)[i];
    __half2* d = reinterpret_cast<__half2*>(g_wh + off) + 2 * i;
    d[0] = __floats2half2_rn(v.x, v.y);
    d[1] = __floats2half2_rn(v.z, v.w);
}

// ---------------------------------------------------------------------------
// Fused layer-1: H[128 tok x 128 hid tile] = silu(X Gw^T) * (X Uw^T)
// CTA 128x128x32 (fp16), 512 threads, 16 warps (warp tile 32x32 both matrices),
// 4-stage cp.async pipeline, 24KB/stage (A 8K | Bg 8K | Bu 8K).
// ---------------------------------------------------------------------------
#define UPSTG 24576
template <bool GATHER>
__global__ void __launch_bounds__(512, 1)
up_kernel(int H, int expert, int gw_off, int uw_off) {
    extern __shared__ __align__(16) char smem[];
    const int tid = threadIdx.x, lane = tid & 31, wid = tid >> 5;
    const int wm = wid & 3, wn = wid >> 2;
    const int m0 = blockIdx.y * 128;
    const int n0 = blockIdx.x * 128;
    const int M = GATHER ? g_count[expert] : N_TOK;
    if (m0 >= M) return;
    const __half* gw = g_wh + gw_off;
    const __half* uw = g_wh + uw_off;
    const uint32_t sb0 = smem_u32(smem);

    // ---- producer addressing: thread t -> row t/4, 16B seg t%4 ------------
    const int row = tid >> 2, seg = tid & 3;
    int p = min(m0 + row, M - 1);
    if (GATHER) p = g_idx[expert][p];
    const __half* aptr = g_xh + (size_t)p * C_DIM + seg * 8;
    const int rb = min(n0 + row, H - 1);
    const __half* gptr = gw + (size_t)rb * C_DIM + seg * 8;
    const __half* uptr = uw + (size_t)rb * C_DIM + seg * 8;
    const uint32_t soff = (uint32_t)row * 64u + (uint32_t)((seg ^ (row & 3)) << 4);

    // ---- fragment addressing constants ------------------------------------
    const int lm = lane >> 3, lr = lane & 7;
    const int selA = lm >> 1, selB = lm & 1;
    uint32_t a_rt[2], a_rs[2], b_rt[2], b_rs[2];
#pragma unroll
    for (int mi = 0; mi < 2; ++mi) {
        int r = wm * 32 + mi * 16 + (lm & 1) * 8 + lr;
        a_rt[mi] = (uint32_t)r * 64u; a_rs[mi] = (uint32_t)(r & 3);
    }
#pragma unroll
    for (int t = 0; t < 2; ++t) {
        int r = wn * 32 + t * 16 + (lm >> 1) * 8 + lr;
        b_rt[t] = (uint32_t)r * 64u; b_rs[t] = (uint32_t)(r & 3);
    }

    float accg[2][4][4] = {}, accu[2][4][4] = {};
    const int KT = C_DIM / 32;  // 28

    auto prefetch = [&](int kt, int st) {
        uint32_t sb = sb0 + (uint32_t)st * UPSTG;
        cp16(sb + soff,          aptr + kt * 32);
        cp16(sb + 8192u + soff,  gptr + kt * 32);
        cp16(sb + 16384u + soff, uptr + kt * 32);
        cp_commit();
    };
#pragma unroll
    for (int s = 0; s < 3; ++s) prefetch(s, s);

    for (int kt = 0; kt < KT; ++kt) {
        cp_wait<2>();
        __syncthreads();
        if (kt + 3 < KT) prefetch(kt + 3, (kt + 3) & 3);
        else cp_commit();
        const uint32_t As = sb0 + (uint32_t)(kt & 3) * UPSTG;
        const uint32_t Bg = As + 8192u, Bu = As + 16384u;
#pragma unroll
        for (int j = 0; j < 2; ++j) {
            uint32_t a[2][4], bg[2][4], bu[2][4];
#pragma unroll
            for (int mi = 0; mi < 2; ++mi)
                ldsm4(a[mi], As + a_rt[mi] + ((((j << 1) | selA) ^ a_rs[mi]) << 4));
#pragma unroll
            for (int t = 0; t < 2; ++t) {
                uint32_t so = ((((j << 1) | selB) ^ b_rs[t]) << 4);
                ldsm4(bg[t], Bg + b_rt[t] + so);
                ldsm4(bu[t], Bu + b_rt[t] + so);
            }
#pragma unroll
            for (int mi = 0; mi < 2; ++mi)
#pragma unroll
                for (int ni = 0; ni < 4; ++ni) {
                    int t = ni >> 1, hi = (ni & 1) * 2;
                    mma16816(accg[mi][ni], a[mi], bg[t][hi], bg[t][hi + 1]);
                    mma16816(accu[mi][ni], a[mi], bu[t][hi], bu[t][hi + 1]);
                }
        }
    }

    // ---- epilogue: silu(g)*u -> fp16 scratch (indexed by position) --------
#pragma unroll
    for (int mi = 0; mi < 2; ++mi) {
        int r = wm * 32 + mi * 16 + (lane >> 2);
#pragma unroll
        for (int ni = 0; ni < 4; ++ni) {
            int nc = n0 + wn * 32 + ni * 8 + ((lane & 3) << 1);
            if (nc >= H) continue;
            const float* g4 = accg[mi][ni];
            const float* u4 = accu[mi][ni];
            int p0 = m0 + r;
            if (p0 < M) {
                __half2 h = __floats2half2_rn(silu_f(g4[0]) * u4[0], silu_f(g4[1]) * u4[1]);
                *reinterpret_cast<__half2*>(g_hh + (size_t)p0 * H + nc) = h;
            }
            int p1 = p0 + 8;
            if (p1 < M) {
                __half2 h = __floats2half2_rn(silu_f(g4[2]) * u4[2], silu_f(g4[3]) * u4[3]);
                *reinterpret_cast<__half2*>(g_hh + (size_t)p1 * H + nc) = h;
            }
        }
    }
}

// ---------------------------------------------------------------------------
// Down projection: D[128 tok x 128 c tile] = H . Dw^T
// base: out[t] = x[t] + D;  experts: out[idx[p]] += D.
// 4-stage pipeline, 16KB/stage (A 8K | B 8K).
// ---------------------------------------------------------------------------
#define DNSTG 16384
template <bool GATHER>
__global__ void __launch_bounds__(512, 1)
down_kernel(int K, int expert, int dw_off,
            const float* __restrict__ x, float* __restrict__ out) {
    extern __shared__ __align__(16) char smem[];
    const int tid = threadIdx.x, lane = tid & 31, wid = tid >> 5;
    const int wm = wid & 3, wn = wid >> 2;
    const int m0 = blockIdx.y * 128;
    const int n0 = blockIdx.x * 128;
    const int M = GATHER ? g_count[expert] : N_TOK;
    if (m0 >= M) return;
    const __half* dw = g_wh + dw_off;
    const uint32_t sb0 = smem_u32(smem);

    const int row = tid >> 2, seg = tid & 3;
    const int p = min(m0 + row, M - 1);
    const __half* aptr = g_hh + (size_t)p * K + seg * 8;
    const __half* bptr = dw + (size_t)(n0 + row) * K + seg * 8;
    const uint32_t soff = (uint32_t)row * 64u + (uint32_t)((seg ^ (row & 3)) << 4);

    const int lm = lane >> 3, lr = lane & 7;
    const int selA = lm >> 1, selB = lm & 1;
    uint32_t a_rt[2], a_rs[2], b_rt[2], b_rs[2];
#pragma unroll
    for (int mi = 0; mi < 2; ++mi) {
        int r = wm * 32 + mi * 16 + (lm & 1) * 8 + lr;
        a_rt[mi] = (uint32_t)r * 64u; a_rs[mi] = (uint32_t)(r & 3);
    }
#pragma unroll
    for (int t = 0; t < 2; ++t) {
        int r = wn * 32 + t * 16 + (lm >> 1) * 8 + lr;
        b_rt[t] = (uint32_t)r * 64u; b_rs[t] = (uint32_t)(r & 3);
    }

    float acc[2][4][4] = {};
    const int KT = K / 32;

    auto prefetch = [&](int kt, int st) {
        uint32_t sb = sb0 + (uint32_t)st * DNSTG;
        cp16(sb + soff,         aptr + kt * 32);
        cp16(sb + 8192u + soff, bptr + kt * 32);
        cp_commit();
    };
#pragma unroll
    for (int s = 0; s < 3; ++s) prefetch(s, s);

    for (int kt = 0; kt < KT; ++kt) {
        cp_wait<2>();
        __syncthreads();
        if (kt + 3 < KT) prefetch(kt + 3, (kt + 3) & 3);
        else cp_commit();
        const uint32_t As = sb0 + (uint32_t)(kt & 3) * DNSTG;
        const uint32_t Bs = As + 8192u;
#pragma unroll
        for (int j = 0; j < 2; ++j) {
            uint32_t a[2][4], b[2][4];
#pragma unroll
            for (int mi = 0; mi < 2; ++mi)
                ldsm4(a[mi], As + a_rt[mi] + ((((j << 1) | selA) ^ a_rs[mi]) << 4));
#pragma unroll
            for (int t = 0; t < 2; ++t)
                ldsm4(b[t], Bs + b_rt[t] + ((((j << 1) | selB) ^ b_rs[t]) << 4));
#pragma unroll
            for (int mi = 0; mi < 2; ++mi)
#pragma unroll
                for (int ni = 0; ni < 4; ++ni) {
                    int t = ni >> 1, hi = (ni & 1) * 2;
                    mma16816(acc[mi][ni], a[mi], b[t][hi], b[t][hi + 1]);
                }
        }
    }

    // ---- epilogue: residual add / accumulate ------------------------------
#pragma unroll
    for (int mi = 0; mi < 2; ++mi) {
        int r = wm * 32 + mi * 16 + (lane >> 2);
#pragma unroll
        for (int ni = 0; ni < 4; ++ni) {
            int c = n0 + wn * 32 + ni * 8 + ((lane & 3) << 1);
            const float* a4 = acc[mi][ni];
#pragma unroll
            for (int half = 0; half < 2; ++half) {
                int pp = m0 + r + half * 8;
                if (pp >= M) continue;
                int tok = GATHER ? g_idx[expert][pp] : pp;
                float* orow = out + (size_t)tok * C_DIM + c;
                float2 v;
                if (GATHER) v = *reinterpret_cast<const float2*>(orow);
                else        v = *reinterpret_cast<const float2*>(x + (size_t)tok * C_DIM + c);
                v.x += a4[half * 2 + 0];
                v.y += a4[half * 2 + 1];
                *reinterpret_cast<float2*>(orow) = v;
            }
        }
    }
}

// ---------------------------------------------------------------------------
extern "C" void kernel_launch(void* const* d_in, const int* in_sizes, int n_in,
                              void* d_out, int out_size) {
    const float* x    = (const float*)d_in[0];
    const float* bgw  = (const float*)d_in[1];
    const float* buw  = (const float*)d_in[2];
    const float* bdw  = (const float*)d_in[3];
    const float* rw   = (const float*)d_in[4];
    const float* bias = (const float*)d_in[5];
    const float* egw[NEXP] = {(const float*)d_in[6],  (const float*)d_in[9],  (const float*)d_in[12]};
    const float* euw[NEXP] = {(const float*)d_in[7],  (const float*)d_in[10], (const float*)d_in[13]};
    const float* edw[NEXP] = {(const float*)d_in[8],  (const float*)d_in[11], (const float*)d_in[14]};
    float* out = (float*)d_out;
    const int He[NEXP]    = {1152, 1344, 1536};
    const int GOFF[NEXP]  = {OFF_E0G, OFF_E1G, OFF_E2G};
    const int UOFF[NEXP]  = {OFF_E0U, OFF_E1U, OFF_E2U};
    const int DOFF[NEXP]  = {OFF_E0D, OFF_E1D, OFF_E2D};

    const int UP_SMEM = 4 * UPSTG;   // 98304
    const int DN_SMEM = 4 * DNSTG;   // 65536
    cudaFuncSetAttribute(up_kernel<false>,   cudaFuncAttributeMaxDynamicSharedMemorySize, UP_SMEM);
    cudaFuncSetAttribute(up_kernel<true>,    cudaFuncAttributeMaxDynamicSharedMemorySize, UP_SMEM);
    cudaFuncSetAttribute(down_kernel<false>, cudaFuncAttributeMaxDynamicSharedMemorySize, DN_SMEM);
    cudaFuncSetAttribute(down_kernel<true>,  cudaFuncAttributeMaxDynamicSharedMemorySize, DN_SMEM);

    // routing + fp16 conversion
    zero_counts_kernel<<<1, 32>>>();
    router_kernel<<<N_TOK / 8, dim3(32, 8)>>>(x, rw, bias);

    auto cvt_blocks = [](int n) { return (n / 4 + 255) / 256; };
    {
        int nx = N_TOK * C_DIM;
        cvt_x_kernel<<<cvt_blocks(nx), 256>>>(x, nx / 4);
        int nb = 1152 * C_DIM;
        cvt_w_kernel<<<cvt_blocks(nb), 256>>>(bgw, OFF_BG, nb / 4);
        cvt_w_kernel<<<cvt_blocks(nb), 256>>>(buw, OFF_BU, nb / 4);
        cvt_w_kernel<<<cvt_blocks(nb), 256>>>(bdw, OFF_BD, nb / 4);
        for (int e = 0; e < NEXP; ++e) {
            int ne = He[e] * C_DIM;
            cvt_w_kernel<<<cvt_blocks(ne), 256>>>(egw[e], GOFF[e], ne / 4);
            cvt_w_kernel<<<cvt_blocks(ne), 256>>>(euw[e], UOFF[e], ne / 4);
            cvt_w_kernel<<<cvt_blocks(ne), 256>>>(edw[e], DOFF[e], ne / 4);
        }
    }

    // base
    up_kernel<false><<<dim3(1152 / 128, N_TOK / 128), 512, UP_SMEM>>>(1152, 0, OFF_BG, OFF_BU);
    down_kernel<false><<<dim3(C_DIM / 128, N_TOK / 128), 512, DN_SMEM>>>(1152, 0, OFF_BD, x, out);

    // experts (sequential; g_hh reused)
    for (int e = 0; e < NEXP; ++e) {
        int ntiles = (He[e] + 127) / 128;
        up_kernel<true><<<dim3(ntiles, N_TOK / 128), 512, UP_SMEM>>>(He[e], e, GOFF[e], UOFF[e]);
        down_kernel<true><<<dim3(C_DIM / 128, N_TOK / 128), 512, DN_SMEM>>>(He[e], e, DOFF[e], x, out);
    }
}

// round 7
// speedup vs baseline: 2.0840x; 1.3869x over previous
#include <cuda_runtime.h>
#include <cuda_fp16.h>
#include <cstdint>
#include <math.h>

// ---------------------------------------------------------------------------
// PyramidResidualMoE, sm_100 legacy tensor path:
// fp16 mma.m16n8k16 + ldmatrix + cp.async (BK=64, 4-stage).
// out = x + baseSwiGLU(x) + expert_{argmax}(x)   (router weight provably 1.0)
// ---------------------------------------------------------------------------

#define N_TOK 16384
#define C_DIM 896
#define HMAX  1536
#define NEXP  3

__device__ __half g_xh[(size_t)N_TOK * C_DIM];
__device__ __half g_hh[(size_t)N_TOK * HMAX];
__device__ __half g_wh[13934592];
__device__ int    g_idx[NEXP][N_TOK];
__device__ int    g_count[NEXP];

// offsets into g_wh (halves)
#define OFF_BG  0
#define OFF_BU  1032192
#define OFF_BD  2064384
#define OFF_E0G 3096576
#define OFF_E0U 4128768
#define OFF_E0D 5160960
#define OFF_E1G 6193152
#define OFF_E1U 7397376
#define OFF_E1D 8601600
#define OFF_E2G 9805824
#define OFF_E2U 11182080
#define OFF_E2D 12558336

// ---------------------------- PTX helpers ----------------------------------
__device__ __forceinline__ uint32_t smem_u32(const void* p) {
    uint32_t a;
    asm("{ .reg .u64 t; cvta.to.shared.u64 t, %1; cvt.u32.u64 %0, t; }" : "=r"(a) : "l"(p));
    return a;
}
__device__ __forceinline__ void cp16(uint32_t d, const void* s) {
    asm volatile("cp.async.cg.shared.global [%0], [%1], 16;" :: "r"(d), "l"(s) : "memory");
}
__device__ __forceinline__ void cp_commit() { asm volatile("cp.async.commit_group;" ::: "memory"); }
template<int N> __device__ __forceinline__ void cp_wait() {
    asm volatile("cp.async.wait_group %0;" :: "n"(N) : "memory");
}
__device__ __forceinline__ void ldsm4(uint32_t* r, uint32_t addr) {
    asm volatile("ldmatrix.sync.aligned.m8n8.x4.shared.b16 {%0,%1,%2,%3}, [%4];"
                 : "=r"(r[0]), "=r"(r[1]), "=r"(r[2]), "=r"(r[3]) : "r"(addr));
}
__device__ __forceinline__ void mma16816(float* c, const uint32_t* a, uint32_t b0, uint32_t b1) {
    asm volatile(
        "mma.sync.aligned.m16n8k16.row.col.f32.f16.f16.f32 "
        "{%0,%1,%2,%3}, {%4,%5,%6,%7}, {%8,%9}, {%0,%1,%2,%3};"
        : "+f"(c[0]), "+f"(c[1]), "+f"(c[2]), "+f"(c[3])
        : "r"(a[0]), "r"(a[1]), "r"(a[2]), "r"(a[3]), "r"(b0), "r"(b1));
}
__device__ __forceinline__ float silu_f(float g) { return g / (1.f + expf(-g)); }

// ---------------------------------------------------------------------------
__global__ void zero_counts_kernel() {
    if (threadIdx.x < NEXP) g_count[threadIdx.x] = 0;
}

__global__ void router_kernel(const float* __restrict__ x,
                              const float* __restrict__ rw,
                              const float* __restrict__ bias) {
    int tok  = blockIdx.x * blockDim.y + threadIdx.y;
    int lane = threadIdx.x;
    if (tok >= N_TOK) return;
    const float* xr = x + (size_t)tok * C_DIM;
    float s0 = 0.f, s1 = 0.f, s2 = 0.f;
    for (int c = lane; c < C_DIM; c += 32) {
        float xv = xr[c];
        s0 = fmaf(xv, rw[c], s0);
        s1 = fmaf(xv, rw[C_DIM + c], s1);
        s2 = fmaf(xv, rw[2 * C_DIM + c], s2);
    }
#pragma unroll
    for (int o = 16; o > 0; o >>= 1) {
        s0 += __shfl_xor_sync(0xffffffffu, s0, o);
        s1 += __shfl_xor_sync(0xffffffffu, s1, o);
        s2 += __shfl_xor_sync(0xffffffffu, s2, o);
    }
    if (lane == 0) {
        float l0 = s0 + bias[0], l1 = s1 + bias[1], l2 = s2 + bias[2];
        int best = 0; float bv = l0;
        if (l1 > bv) { best = 1; bv = l1; }
        if (l2 > bv) { best = 2; bv = l2; }
        int pos = atomicAdd(&g_count[best], 1);
        g_idx[best][pos] = tok;
    }
}

// ------------------------- fused fp32->fp16 convert -------------------------
#define NCVT 13
struct __align__(8) CvtAll {
    const float* src[NCVT];
    int off[NCVT];     // halves into g_wh; -1 => g_xh
    int cum[NCVT + 1]; // cumulative float4 counts
};
__global__ void cvt_all_kernel(CvtAll a) {
    int i = blockIdx.x * 256 + threadIdx.x;
    if (i >= a.cum[NCVT]) return;
    int s = 0;
#pragma unroll
    for (int k = 1; k < NCVT; ++k) s += (i >= a.cum[k]);
    int li = i - a.cum[s];
    float4 v = reinterpret_cast<const float4*>(a.src[s])[li];
    __half2* d = (a.off[s] < 0 ? reinterpret_cast<__half2*>(g_xh)
                               : reinterpret_cast<__half2*>(g_wh + a.off[s])) + 2 * li;
    d[0] = __floats2half2_rn(v.x, v.y);
    d[1] = __floats2half2_rn(v.z, v.w);
}

// ---------------------------------------------------------------------------
// Fused layer-1: H[128 tok x 128 hid tile] = silu(X Gw^T) * (X Uw^T)
// CTA 128x128x64, 512 threads / 16 warps (warp tile 32x32), 4-stage cp.async.
// Stage 48KB: A 16K | Bg 16K | Bu 16K.  Rows are 128B, 8-way XOR swizzled.
// ---------------------------------------------------------------------------
#define UPSTG 49152
template <bool GATHER>
__global__ void __launch_bounds__(512, 1)
up_kernel(int H, int expert, int gw_off, int uw_off) {
    extern __shared__ __align__(16) char smem[];
    const int tid = threadIdx.x, lane = tid & 31, wid = tid >> 5;
    const int wm = wid & 3, wn = wid >> 2;
    const int m0 = blockIdx.y * 128;
    const int n0 = blockIdx.x * 128;
    const int M = GATHER ? g_count[expert] : N_TOK;
    if (m0 >= M) return;
    const __half* gw = g_wh + gw_off;
    const __half* uw = g_wh + uw_off;
    const uint32_t sb0 = smem_u32(smem);

    // ---- producer: thread -> row tid/4, segs (tid&3) and (tid&3)+4 --------
    const int row = tid >> 2, s0g = tid & 3;
    int p = min(m0 + row, M - 1);
    if (GATHER) p = g_idx[expert][p];
    const __half* aptr = g_xh + (size_t)p * C_DIM;
    const int rb = min(n0 + row, H - 1);
    const __half* gptr = gw + (size_t)rb * C_DIM;
    const __half* uptr = uw + (size_t)rb * C_DIM;
    const uint32_t so0 = (uint32_t)row * 128u + (uint32_t)((s0g ^ (row & 7)) << 4);
    const uint32_t so1 = (uint32_t)row * 128u + (uint32_t)(((s0g + 4) ^ (row & 7)) << 4);
    const int g0 = s0g * 8, g1 = (s0g + 4) * 8;   // gmem half offsets

    // ---- fragment addressing ----------------------------------------------
    const int lm = lane >> 3, lr = lane & 7;
    const int selA = lm >> 1, selB = lm & 1;
    uint32_t a_rt[2], a_rs[2], b_rt[2], b_rs[2];
#pragma unroll
    for (int mi = 0; mi < 2; ++mi) {
        int r = wm * 32 + mi * 16 + (lm & 1) * 8 + lr;
        a_rt[mi] = (uint32_t)r * 128u; a_rs[mi] = (uint32_t)(r & 7);
    }
#pragma unroll
    for (int t = 0; t < 2; ++t) {
        int r = wn * 32 + t * 16 + (lm >> 1) * 8 + lr;
        b_rt[t] = (uint32_t)r * 128u; b_rs[t] = (uint32_t)(r & 7);
    }

    float accg[2][4][4] = {}, accu[2][4][4] = {};
    const int KT = C_DIM / 64;  // 14

    auto prefetch = [&](int kt, int st) {
        uint32_t sb = sb0 + (uint32_t)st * UPSTG;
        int k = kt * 64;
        cp16(sb + so0,          aptr + k + g0);
        cp16(sb + so1,          aptr + k + g1);
        cp16(sb + 16384u + so0, gptr + k + g0);
        cp16(sb + 16384u + so1, gptr + k + g1);
        cp16(sb + 32768u + so0, uptr + k + g0);
        cp16(sb + 32768u + so1, uptr + k + g1);
        cp_commit();
    };
#pragma unroll
    for (int s = 0; s < 3; ++s) prefetch(s, s);

    for (int kt = 0; kt < KT; ++kt) {
        cp_wait<2>();
        __syncthreads();
        if (kt + 3 < KT) prefetch(kt + 3, (kt + 3) & 3);
        else cp_commit();
        const uint32_t As = sb0 + (uint32_t)(kt & 3) * UPSTG;
        const uint32_t Bg = As + 16384u, Bu = As + 32768u;
#pragma unroll
        for (int j = 0; j < 4; ++j) {
            uint32_t a[2][4], bg[2][4], bu[2][4];
#pragma unroll
            for (int mi = 0; mi < 2; ++mi)
                ldsm4(a[mi], As + a_rt[mi] + ((((j << 1) | selA) ^ a_rs[mi]) << 4));
#pragma unroll
            for (int t = 0; t < 2; ++t) {
                uint32_t ch = (uint32_t)((j << 1) | selB);
                ldsm4(bg[t], Bg + b_rt[t] + ((ch ^ b_rs[t]) << 4));
                ldsm4(bu[t], Bu + b_rt[t] + ((ch ^ b_rs[t]) << 4));
            }
#pragma unroll
            for (int mi = 0; mi < 2; ++mi)
#pragma unroll
                for (int ni = 0; ni < 4; ++ni) {
                    int t = ni >> 1, hi = (ni & 1) * 2;
                    mma16816(accg[mi][ni], a[mi], bg[t][hi], bg[t][hi + 1]);
                    mma16816(accu[mi][ni], a[mi], bu[t][hi], bu[t][hi + 1]);
                }
        }
    }

    // ---- epilogue: silu(g)*u -> fp16 scratch (indexed by position) --------
#pragma unroll
    for (int mi = 0; mi < 2; ++mi) {
        int r = wm * 32 + mi * 16 + (lane >> 2);
#pragma unroll
        for (int ni = 0; ni < 4; ++ni) {
            int nc = n0 + wn * 32 + ni * 8 + ((lane & 3) << 1);
            if (nc >= H) continue;
            const float* g4 = accg[mi][ni];
            const float* u4 = accu[mi][ni];
            int p0 = m0 + r;
            if (p0 < M) {
                __half2 h = __floats2half2_rn(silu_f(g4[0]) * u4[0], silu_f(g4[1]) * u4[1]);
                *reinterpret_cast<__half2*>(g_hh + (size_t)p0 * H + nc) = h;
            }
            int p1 = p0 + 8;
            if (p1 < M) {
                __half2 h = __floats2half2_rn(silu_f(g4[2]) * u4[2], silu_f(g4[3]) * u4[3]);
                *reinterpret_cast<__half2*>(g_hh + (size_t)p1 * H + nc) = h;
            }
        }
    }
}

// ---------------------------------------------------------------------------
// Down projection: D[128 tok x 128 c] = H . Dw^T
// base: out = x + D;  experts: out[idx[p]] += D.  4-stage, 32KB/stage.
// ---------------------------------------------------------------------------
#define DNSTG 32768
template <bool GATHER>
__global__ void __launch_bounds__(512, 1)
down_kernel(int K, int expert, int dw_off,
            const float* __restrict__ x, float* __restrict__ out) {
    extern __shared__ __align__(16) char smem[];
    const int tid = threadIdx.x, lane = tid & 31, wid = tid >> 5;
    const int wm = wid & 3, wn = wid >> 2;
    const int m0 = blockIdx.y * 128;
    const int n0 = blockIdx.x * 128;
    const int M = GATHER ? g_count[expert] : N_TOK;
    if (m0 >= M) return;
    const __half* dw = g_wh + dw_off;
    const uint32_t sb0 = smem_u32(smem);

    const int row = tid >> 2, s0g = tid & 3;
    const int p = min(m0 + row, M - 1);
    const __half* aptr = g_hh + (size_t)p * K;
    const __half* bptr = dw + (size_t)(n0 + row) * K;
    const uint32_t so0 = (uint32_t)row * 128u + (uint32_t)((s0g ^ (row & 7)) << 4);
    const uint32_t so1 = (uint32_t)row * 128u + (uint32_t)(((s0g + 4) ^ (row & 7)) << 4);
    const int g0 = s0g * 8, g1 = (s0g + 4) * 8;

    const int lm = lane >> 3, lr = lane & 7;
    const int selA = lm >> 1, selB = lm & 1;
    uint32_t a_rt[2], a_rs[2], b_rt[2], b_rs[2];
#pragma unroll
    for (int mi = 0; mi < 2; ++mi) {
        int r = wm * 32 + mi * 16 + (lm & 1) * 8 + lr;
        a_rt[mi] = (uint32_t)r * 128u; a_rs[mi] = (uint32_t)(r & 7);
    }
#pragma unroll
    for (int t = 0; t < 2; ++t) {
        int r = wn * 32 + t * 16 + (lm >> 1) * 8 + lr;
        b_rt[t] = (uint32_t)r * 128u; b_rs[t] = (uint32_t)(r & 7);
    }

    float acc[2][4][4] = {};
    const int KT = K / 64;

    auto prefetch = [&](int kt, int st) {
        uint32_t sb = sb0 + (uint32_t)st * DNSTG;
        int k = kt * 64;
        cp16(sb + so0,          aptr + k + g0);
        cp16(sb + so1,          aptr + k + g1);
        cp16(sb + 16384u + so0, bptr + k + g0);
        cp16(sb + 16384u + so1, bptr + k + g1);
        cp_commit();
    };
#pragma unroll
    for (int s = 0; s < 3; ++s) prefetch(s, s);

    for (int kt = 0; kt < KT; ++kt) {
        cp_wait<2>();
        __syncthreads();
        if (kt + 3 < KT) prefetch(kt + 3, (kt + 3) & 3);
        else cp_commit();
        const uint32_t As = sb0 + (uint32_t)(kt & 3) * DNSTG;
        const uint32_t Bs = As + 16384u;
#pragma unroll
        for (int j = 0; j < 4; ++j) {
            uint32_t a[2][4], b[2][4];
#pragma unroll
            for (int mi = 0; mi < 2; ++mi)
                ldsm4(a[mi], As + a_rt[mi] + ((((j << 1) | selA) ^ a_rs[mi]) << 4));
#pragma unroll
            for (int t = 0; t < 2; ++t)
                ldsm4(b[t], Bs + b_rt[t] + ((((uint32_t)((j << 1) | selB)) ^ b_rs[t]) << 4));
#pragma unroll
            for (int mi = 0; mi < 2; ++mi)
#pragma unroll
                for (int ni = 0; ni < 4; ++ni) {
                    int t = ni >> 1, hi = (ni & 1) * 2;
                    mma16816(acc[mi][ni], a[mi], b[t][hi], b[t][hi + 1]);
                }
        }
    }

#pragma unroll
    for (int mi = 0; mi < 2; ++mi) {
        int r = wm * 32 + mi * 16 + (lane >> 2);
#pragma unroll
        for (int ni = 0; ni < 4; ++ni) {
            int c = n0 + wn * 32 + ni * 8 + ((lane & 3) << 1);
            const float* a4 = acc[mi][ni];
#pragma unroll
            for (int half = 0; half < 2; ++half) {
                int pp = m0 + r + half * 8;
                if (pp >= M) continue;
                int tok = GATHER ? g_idx[expert][pp] : pp;
                float* orow = out + (size_t)tok * C_DIM + c;
                float2 v;
                if (GATHER) v = *reinterpret_cast<const float2*>(orow);
                else        v = *reinterpret_cast<const float2*>(x + (size_t)tok * C_DIM + c);
                v.x += a4[half * 2 + 0];
                v.y += a4[half * 2 + 1];
                *reinterpret_cast<float2*>(orow) = v;
            }
        }
    }
}

// ---------------------------------------------------------------------------
extern "C" void kernel_launch(void* const* d_in, const int* in_sizes, int n_in,
                              void* d_out, int out_size) {
    const float* x    = (const float*)d_in[0];
    const float* bgw  = (const float*)d_in[1];
    const float* buw  = (const float*)d_in[2];
    const float* bdw  = (const float*)d_in[3];
    const float* rw   = (const float*)d_in[4];
    const float* bias = (const float*)d_in[5];
    const float* egw[NEXP] = {(const float*)d_in[6],  (const float*)d_in[9],  (const float*)d_in[12]};
    const float* euw[NEXP] = {(const float*)d_in[7],  (const float*)d_in[10], (const float*)d_in[13]};
    const float* edw[NEXP] = {(const float*)d_in[8],  (const float*)d_in[11], (const float*)d_in[14]};
    float* out = (float*)d_out;
    const int He[NEXP]   = {1152, 1344, 1536};
    const int GOFF[NEXP] = {OFF_E0G, OFF_E1G, OFF_E2G};
    const int UOFF[NEXP] = {OFF_E0U, OFF_E1U, OFF_E2U};
    const int DOFF[NEXP] = {OFF_E0D, OFF_E1D, OFF_E2D};

    const int UP_SMEM = 4 * UPSTG;   // 196608
    const int DN_SMEM = 4 * DNSTG;   // 131072
    cudaFuncSetAttribute(up_kernel<false>,   cudaFuncAttributeMaxDynamicSharedMemorySize, UP_SMEM);
    cudaFuncSetAttribute(up_kernel<true>,    cudaFuncAttributeMaxDynamicSharedMemorySize, UP_SMEM);
    cudaFuncSetAttribute(down_kernel<false>, cudaFuncAttributeMaxDynamicSharedMemorySize, DN_SMEM);
    cudaFuncSetAttribute(down_kernel<true>,  cudaFuncAttributeMaxDynamicSharedMemorySize, DN_SMEM);

    // (1) zero, (2) router
    zero_counts_kernel<<<1, 32>>>();
    router_kernel<<<N_TOK / 8, dim3(32, 8)>>>(x, rw, bias);

    // (3) fused fp32->fp16 convert: x + 12 weight tensors in one kernel
    CvtAll ca;
    const float* srcs[NCVT] = {x, bgw, buw, bdw,
                               egw[0], euw[0], edw[0],
                               egw[1], euw[1], edw[1],
                               egw[2], euw[2], edw[2]};
    const int offs[NCVT] = {-1, OFF_BG, OFF_BU, OFF_BD,
                            OFF_E0G, OFF_E0U, OFF_E0D,
                            OFF_E1G, OFF_E1U, OFF_E1D,
                            OFF_E2G, OFF_E2U, OFF_E2D};
    const int sizes[NCVT] = {N_TOK * C_DIM,
                             1152 * C_DIM, 1152 * C_DIM, 1152 * C_DIM,
                             1152 * C_DIM, 1152 * C_DIM, 1152 * C_DIM,
                             1344 * C_DIM, 1344 * C_DIM, 1344 * C_DIM,
                             1536 * C_DIM, 1536 * C_DIM, 1536 * C_DIM};
    int cum = 0;
    for (int i = 0; i < NCVT; ++i) {
        ca.src[i] = srcs[i]; ca.off[i] = offs[i]; ca.cum[i] = cum;
        cum += sizes[i] / 4;
    }
    ca.cum[NCVT] = cum;
    cvt_all_kernel<<<(cum + 255) / 256, 256>>>(ca);

    // (4) base up, (5) base down, (6) expert0 up <- ncu captures this one
    up_kernel<false><<<dim3(1152 / 128, N_TOK / 128), 512, UP_SMEM>>>(1152, 0, OFF_BG, OFF_BU);
    down_kernel<false><<<dim3(C_DIM / 128, N_TOK / 128), 512, DN_SMEM>>>(1152, 0, OFF_BD, x, out);

    for (int e = 0; e < NEXP; ++e) {
        int ntiles = (He[e] + 127) / 128;
        up_kernel<true><<<dim3(ntiles, N_TOK / 128), 512, UP_SMEM>>>(He[e], e, GOFF[e], UOFF[e]);
        down_kernel<true><<<dim3(C_DIM / 128, N_TOK / 128), 512, DN_SMEM>>>(He[e], e, DOFF[e], x, out);
    }
}